// round 15
// baseline (speedup 1.0000x reference)
#include <cuda_runtime.h>
#include <cstdint>
#include <math.h>

#define NA 80000
#define NE 250000
#define NG 2000
#define APG 40

// ---------------- device scratch (no allocation allowed) ---------------------
__device__ float g_Ah[NA * 256];
__device__ float g_Eh[NA * 256];
__device__ float g_Cu[NG * 256];
__device__ float g_Fu[NG * 256];
__device__ float g_esumG[NG * 256];   // per-graph e2 sums; zero-restored by graph_collect
__device__ float g_Wt[6 * 256 * 256]; // slots 0..5, K-major, k-pair-permuted, tf32-rounded
__device__ float g_Wcat[256 * 768];   // [n][k] = W6|W7|W8 K-major, permuted, tf32-rounded
__device__ float g_bias[6 * 256];
__device__ float g_bcat[256];         // b6+b7+b8
__device__ float g_Acat[NG * 768];    // [Sh/40 | Se/deg | u]
__device__ double g_sumB[8][768];     // banked stats; zero-restored by bn_finalize
__device__ double g_sumsqB[8][768];
__device__ float g_bnA[256];
__device__ float g_bnB[256];
__device__ int g_cnt[NA];             // CSR: zeroed by transpose_W, hist, then cursor
__device__ int g_rowptr[NA + 1];
__device__ int g_eidx[NE];

// orig W idx -> slot:  W0->0(A) W1->3(B) W2->4(C) W3->1(D) W4->2(E) W5->5(F)
__constant__ int c_slot6[6] = {0, 3, 4, 1, 2, 5};

// ---------------- helpers -----------------------------------------------------
__device__ __forceinline__ uint32_t smem_u32(const void* p) {
    uint32_t a;
    asm("{ .reg .u64 t; cvta.to.shared.u64 t, %1; cvt.u32.u64 %0, t; }" : "=r"(a) : "l"(p));
    return a;
}
__device__ __forceinline__ uint32_t f2tf32(float v) {
    uint32_t u;
    asm("cvt.rna.tf32.f32 %0, %1;" : "=r"(u) : "f"(v));
    return u;
}
__device__ __forceinline__ void red_add_v4(float* addr, float a, float b, float c, float d) {
    asm volatile("red.global.add.v4.f32 [%0], {%1, %2, %3, %4};"
        :: "l"(addr), "f"(a), "f"(b), "f"(c), "f"(d) : "memory");
}

// ---------------- tf32 mma GEMM, 3-stage cp.async, swizzled smem -------------
// CTA tile 128x128. grid.y = 2*nSlots: w = y>>1 weight slot, half = y&1.
// Weights are k-pair-permuted per 32-chunk (p = (k%4)*8 + k/4) -> B LDS.64.
// If srcI != nullptr (edge-assemble mode): cooperative epilogue adds
// Ah[src]+Ah[dst]+Cu[gid[src]] and accumulates BN stats (set 1, banked).
__global__ void __launch_bounds__(256, 2) sgemm_tc(
    const float* __restrict__ A, const float* __restrict__ WtG,
    const float* __restrict__ biasG, float* __restrict__ C0,
    float* __restrict__ C1, float* __restrict__ C2, int M, int K,
    const int* __restrict__ srcI, const int* __restrict__ dstI,
    const int* __restrict__ gidI)
{
    extern __shared__ float sm[];
    const int tid  = threadIdx.x;
    const int lane = tid & 31;
    const int wid  = tid >> 5;
    const int wm   = wid & 1;
    const int wn   = wid >> 1;
    const int row0 = blockIdx.x * 128;
    const int w    = blockIdx.y >> 1;
    const int half = blockIdx.y & 1;
    const int col0 = half * 128;
    const int lq   = lane >> 2;
    const int lr   = lane & 3;

    const float* Wt   = WtG + (size_t)w * K * 256;
    const float* bias = biasG + w * 256;
    float* C = (w == 0) ? C0 : ((w == 1) ? C1 : C2);

    const uint32_t smbase = smem_u32(sm);
    const int chunks = K >> 5;

    auto load_chunk = [&](int c) {
        const int st = c % 3;
        const int k0 = c << 5;
        const uint32_t abase = smbase + st * 32768;
        const uint32_t bbase = abase + 16384;
#pragma unroll
        for (int ii = 0; ii < 4; ii++) {
            int i = tid + (ii << 8);
            int r = i >> 3, q = i & 7;
            int grow = row0 + r;
            const float* srcp = A + (size_t)grow * K + k0 + (q << 2);
            uint32_t dstA = abase + (uint32_t)((r << 5) + ((q ^ (r & 7)) << 2)) * 4;
            int sz = (grow < M) ? 16 : 0;
            asm volatile("cp.async.ca.shared.global [%0], [%1], 16, %2;"
                :: "r"(dstA), "l"(srcp), "r"(sz) : "memory");
        }
#pragma unroll
        for (int ii = 0; ii < 4; ii++) {
            int i = tid + (ii << 8);
            int n = i >> 3, q = i & 7;
            const float* srcp = Wt + (size_t)(col0 + n) * K + k0 + (q << 2);
            uint32_t dstB = bbase + (uint32_t)((n << 5) + ((q ^ (n & 7)) << 2)) * 4;
            asm volatile("cp.async.ca.shared.global [%0], [%1], 16;"
                :: "r"(dstB), "l"(srcp) : "memory");
        }
        asm volatile("cp.async.commit_group;" ::: "memory");
    };

    float acc[4][4][4];
#pragma unroll
    for (int i = 0; i < 4; i++)
#pragma unroll
        for (int j = 0; j < 4; j++)
#pragma unroll
            for (int r = 0; r < 4; r++) acc[i][j][r] = 0.f;

    load_chunk(0);
    if (chunks > 1) load_chunk(1);

    for (int c = 0; c < chunks; c++) {
        if (c + 1 < chunks) asm volatile("cp.async.wait_group 1;" ::: "memory");
        else                asm volatile("cp.async.wait_group 0;" ::: "memory");
        __syncthreads();
        if (c + 2 < chunks) load_chunk(c + 2);
        const float* sA = sm + (c % 3) * 8192;
        const float* sB = sA + 4096;

#pragma unroll
        for (int ks = 0; ks < 4; ks++) {
            const int s0 = (((2 * ks) ^ lq) << 2) + lr;
            const int s1 = (((2 * ks + 1) ^ lq) << 2) + lr;
            const int qp   = (lr << 1) + (ks >> 1);
            const int boff = ((qp ^ lq) << 2) + ((ks & 1) << 1);
            uint32_t bf[4][2];
#pragma unroll
            for (int nt = 0; nt < 4; nt++) {
                int n = wn * 32 + nt * 8 + lq;
                float2 b2 = *reinterpret_cast<const float2*>(&sB[(n << 5) + boff]);
                bf[nt][0] = __float_as_uint(b2.x);
                bf[nt][1] = __float_as_uint(b2.y);
            }
#pragma unroll
            for (int mt = 0; mt < 4; mt++) {
                int m = wm * 64 + mt * 16 + lq;
                uint32_t a0 = __float_as_uint(sA[(m << 5) + s0]);
                uint32_t a1 = __float_as_uint(sA[((m + 8) << 5) + s0]);
                uint32_t a2 = __float_as_uint(sA[(m << 5) + s1]);
                uint32_t a3 = __float_as_uint(sA[((m + 8) << 5) + s1]);
#pragma unroll
                for (int nt = 0; nt < 4; nt++) {
                    asm volatile(
                        "mma.sync.aligned.m16n8k8.row.col.f32.tf32.tf32.f32 "
                        "{%0,%1,%2,%3}, {%4,%5,%6,%7}, {%8,%9}, {%0,%1,%2,%3};"
                        : "+f"(acc[mt][nt][0]), "+f"(acc[mt][nt][1]),
                          "+f"(acc[mt][nt][2]), "+f"(acc[mt][nt][3])
                        : "r"(a0), "r"(a1), "r"(a2), "r"(a3),
                          "r"(bf[nt][0]), "r"(bf[nt][1]));
                }
            }
        }
    }

    if (srcI == nullptr) {
#pragma unroll
        for (int nt = 0; nt < 4; nt++) {
            int col = col0 + wn * 32 + nt * 8 + (lr << 1);
            float2 bv = *reinterpret_cast<const float2*>(bias + col);
#pragma unroll
            for (int mt = 0; mt < 4; mt++) {
                int rowa = row0 + wm * 64 + mt * 16 + lq;
                int rowb = rowa + 8;
                if (rowa < M) {
                    float2 o = make_float2(acc[mt][nt][0] + bv.x, acc[mt][nt][1] + bv.y);
                    *reinterpret_cast<float2*>(C + (size_t)rowa * 256 + col) = o;
                }
                if (rowb < M) {
                    float2 o = make_float2(acc[mt][nt][2] + bv.x, acc[mt][nt][3] + bv.y);
                    *reinterpret_cast<float2*>(C + (size_t)rowb * 256 + col) = o;
                }
            }
        }
    } else {
        // ---- cooperative edge-assemble epilogue ----
        float* sC = sm;
        float* sR = sm + 128 * 132;
        __syncthreads();
#pragma unroll
        for (int nt = 0; nt < 4; nt++) {
            int col = wn * 32 + nt * 8 + (lr << 1);
            float2 bv = *reinterpret_cast<const float2*>(bias + col0 + col);
#pragma unroll
            for (int mt = 0; mt < 4; mt++) {
                int ra = wm * 64 + mt * 16 + lq;
                *reinterpret_cast<float2*>(sC + ra * 132 + col) =
                    make_float2(acc[mt][nt][0] + bv.x, acc[mt][nt][1] + bv.y);
                *reinterpret_cast<float2*>(sC + (ra + 8) * 132 + col) =
                    make_float2(acc[mt][nt][2] + bv.x, acc[mt][nt][3] + bv.y);
            }
        }
        __syncthreads();

        const int cbase = lane << 2;
        float s0 = 0.f, s1 = 0.f, s2 = 0.f, s3 = 0.f;
        float p0 = 0.f, p1 = 0.f, p2 = 0.f, p3 = 0.f;
#pragma unroll 4
        for (int i = 0; i < 16; i++) {
            int r = wid * 16 + i;
            int row = row0 + r;
            if (row < M) {
                int s = srcI[row], d = dstI[row];
                int g = gidI[s];
                float4 a4 = *reinterpret_cast<const float4*>(sC + r * 132 + cbase);
                float4 x1 = *reinterpret_cast<const float4*>(g_Ah + (size_t)s * 256 + col0 + cbase);
                float4 x2 = *reinterpret_cast<const float4*>(g_Ah + (size_t)d * 256 + col0 + cbase);
                float4 x3 = *reinterpret_cast<const float4*>(g_Cu + (size_t)g * 256 + col0 + cbase);
                float vx = a4.x + x1.x + x2.x + x3.x;
                float vy = a4.y + x1.y + x2.y + x3.y;
                float vz = a4.z + x1.z + x2.z + x3.z;
                float vw = a4.w + x1.w + x2.w + x3.w;
                __stcs(reinterpret_cast<float4*>(C + (size_t)row * 256 + col0 + cbase),
                       make_float4(vx, vy, vz, vw));
                s0 += vx; p0 += vx * vx;
                s1 += vy; p1 += vy * vy;
                s2 += vz; p2 += vz * vz;
                s3 += vw; p3 += vw * vw;
            }
        }
        sR[wid * 256 + cbase + 0] = s0;
        sR[wid * 256 + cbase + 1] = s1;
        sR[wid * 256 + cbase + 2] = s2;
        sR[wid * 256 + cbase + 3] = s3;
        sR[wid * 256 + 128 + cbase + 0] = p0;
        sR[wid * 256 + 128 + cbase + 1] = p1;
        sR[wid * 256 + 128 + cbase + 2] = p2;
        sR[wid * 256 + 128 + cbase + 3] = p3;
        __syncthreads();
        {
            int c = tid & 127;
            int issq = tid >> 7;
            float acc8 = 0.f;
#pragma unroll
            for (int ww = 0; ww < 8; ww++)
                acc8 += sR[ww * 256 + issq * 128 + c];
            int bank = blockIdx.x & 7;
            if (issq) atomicAdd(&g_sumsqB[bank][256 + col0 + c], (double)acc8);
            else      atomicAdd(&g_sumB[bank][256 + col0 + c], (double)acc8);
        }
    }
}

// ---------------- weight prep (k-pair permutation baked in) + cnt zero -------
__global__ void transpose_W(const float* __restrict__ W, const float* __restrict__ b) {
    int idx = blockIdx.x * 256 + threadIdx.x;
    if (idx < 9 * 65536) {
        int w = idx >> 16;
        int rc = idx & 65535;
        int r = rc >> 8, c = rc & 255;       // r = k, c = n
        float v = __uint_as_float(f2tf32(W[idx]));
        int kin = r & 31;
        int kp  = (r & ~31) + ((kin & 3) << 3) + (kin >> 2);
        if (w < 6) g_Wt[(c_slot6[w] << 16) + (c << 8) + kp] = v;
        else {
            int kglob = (w - 6) * 256 + r;
            int kin2 = kglob & 31;
            int kp2  = (kglob & ~31) + ((kin2 & 3) << 3) + (kin2 >> 2);
            g_Wcat[c * 768 + kp2] = v;
        }
    }
    if (idx < 6 * 256) {
        int w = idx >> 8;
        g_bias[(c_slot6[w] << 8) + (idx & 255)] = b[idx];
    }
    if (idx < 256) {
        g_bcat[idx] = b[6 * 256 + idx] + b[7 * 256 + idx] + b[8 * 256 + idx];
    }
    if (idx < NA) g_cnt[idx] = 0;
}

// ---------------- CSR build ---------------------------------------------------
__global__ void csr_hist(const int* __restrict__ dst) {
    int e = blockIdx.x * blockDim.x + threadIdx.x;
    if (e < NE) atomicAdd(&g_cnt[dst[e]], 1);
}

__global__ void csr_scan() {
    __shared__ int wsum[32];
    __shared__ int carry_s;
    int tid = threadIdx.x, lane = tid & 31, wd = tid >> 5;
    if (tid == 0) carry_s = 0;
    __syncthreads();
    for (int base = 0; base < NA; base += 1024) {
        int i = base + tid;
        int v = (i < NA) ? g_cnt[i] : 0;
        int x = v;
#pragma unroll
        for (int off = 1; off < 32; off <<= 1) {
            int t = __shfl_up_sync(0xffffffff, x, off);
            if (lane >= off) x += t;
        }
        if (lane == 31) wsum[wd] = x;
        __syncthreads();
        if (wd == 0) {
            int wv = wsum[lane];
#pragma unroll
            for (int off = 1; off < 32; off <<= 1) {
                int t = __shfl_up_sync(0xffffffff, wv, off);
                if (lane >= off) wv += t;
            }
            wsum[lane] = wv;
        }
        __syncthreads();
        int warp_excl = (wd == 0) ? 0 : wsum[wd - 1];
        int excl = carry_s + warp_excl + x - v;
        if (i < NA) { g_rowptr[i] = excl; g_cnt[i] = excl; }
        __syncthreads();
        if (tid == 0) carry_s += wsum[31];
        __syncthreads();
    }
    if (tid == 0) g_rowptr[NA] = carry_s;
}

__global__ void csr_fill(const int* __restrict__ dst) {
    int e = blockIdx.x * blockDim.x + threadIdx.x;
    if (e < NE) {
        int p = atomicAdd(&g_cnt[dst[e]], 1);
        g_eidx[p] = e;
    }
}

// ---------------- BN finalize (sums banks, restores zeros) -------------------
__global__ void bn_finalize(int set, int M, const float* __restrict__ gam,
                            const float* __restrict__ bet)
{
    int c = threadIdx.x;
    double s = 0.0, s2 = 0.0;
#pragma unroll
    for (int k = 0; k < 8; k++) {
        s  += g_sumB[k][set * 256 + c];
        s2 += g_sumsqB[k][set * 256 + c];
        g_sumB[k][set * 256 + c] = 0.0;
        g_sumsqB[k][set * 256 + c] = 0.0;
    }
    double mean = s / M;
    double var  = s2 / M - mean * mean;
    float scale = gam[c] * rsqrtf((float)(var + 1e-5));
    g_bnA[c] = scale;
    g_bnB[c] = bet[c] - (float)mean * scale;
}

// -------- fused per-dst: BN(e2)+relu (in place) + gated agg + h2 + stats0 ----
// 2-deep software pipeline: up to two edges' e2/Eh row-pairs in flight,
// doubling per-thread MLP on the gather-dominated chain.
__global__ void __launch_bounds__(256) edge_aggregate(
    float* __restrict__ e2, float* __restrict__ h2,
    const int* __restrict__ src, const int* __restrict__ gid)
{
    __shared__ float sStat[8][256];
    int tid = threadIdx.x;
    int q = tid & 63;
    int slot = tid >> 6;
    int c = q << 2;
    float4 sc = *reinterpret_cast<const float4*>(g_bnA + c);
    float4 bb = *reinterpret_cast<const float4*>(g_bnB + c);
    float s0 = 0.f, s1 = 0.f, s2v = 0.f, s3 = 0.f;
    float p0 = 0.f, p1 = 0.f, p2 = 0.f, p3 = 0.f;

    for (int d = blockIdx.x * 4 + slot; d < NA; d += gridDim.x * 4) {
        int beg = g_rowptr[d], end = g_rowptr[d + 1];
        int n = end - beg;
        float4 nu = make_float4(0.f, 0.f, 0.f, 0.f);
        float4 de = make_float4(0.f, 0.f, 0.f, 0.f);
        float4 se = make_float4(0.f, 0.f, 0.f, 0.f);
        float4 vbuf[2], ebuf[2];
        int ebid[2];
#pragma unroll
        for (int j = 0; j < 2; j++) {
            if (j < n) {
                int eid = g_eidx[beg + j];
                int s = src[eid];
                ebid[j] = eid;
                vbuf[j] = __ldcs(reinterpret_cast<const float4*>(e2 + (size_t)eid * 256 + c));
                ebuf[j] = *reinterpret_cast<const float4*>(g_Eh + (size_t)s * 256 + c);
            }
        }
        for (int i = 0; i < n; i++) {
            int cur = i & 1;
            float4 vc = vbuf[cur], ehc = ebuf[cur];
            int ecur = ebid[cur];
            if (i + 2 < n) {                         // prefetch 2 ahead into freed slot
                int eid = g_eidx[beg + i + 2];
                int s = src[eid];
                ebid[cur] = eid;
                vbuf[cur] = __ldcs(reinterpret_cast<const float4*>(e2 + (size_t)eid * 256 + c));
                ebuf[cur] = *reinterpret_cast<const float4*>(g_Eh + (size_t)s * 256 + c);
            }
            vc.x = fmaxf(vc.x * sc.x + bb.x, 0.f);
            vc.y = fmaxf(vc.y * sc.y + bb.y, 0.f);
            vc.z = fmaxf(vc.z * sc.z + bb.z, 0.f);
            vc.w = fmaxf(vc.w * sc.w + bb.w, 0.f);
            __stcs(reinterpret_cast<float4*>(e2 + (size_t)ecur * 256 + c), vc);
            float g0 = 1.f / (1.f + __expf(-vc.x));
            float g1 = 1.f / (1.f + __expf(-vc.y));
            float g2 = 1.f / (1.f + __expf(-vc.z));
            float g3 = 1.f / (1.f + __expf(-vc.w));
            nu.x += g0 * ehc.x; nu.y += g1 * ehc.y; nu.z += g2 * ehc.z; nu.w += g3 * ehc.w;
            de.x += g0; de.y += g1; de.z += g2; de.w += g3;
            se.x += vc.x; se.y += vc.y; se.z += vc.z; se.w += vc.w;
        }
        int g = gid[d];
        size_t hoff = (size_t)d * 256 + c;
        float4 hv = *reinterpret_cast<const float4*>(h2 + hoff);
        float4 fu = *reinterpret_cast<const float4*>(g_Fu + (size_t)g * 256 + c);
        hv.x += nu.x / (de.x + 1e-6f) + fu.x;
        hv.y += nu.y / (de.y + 1e-6f) + fu.y;
        hv.z += nu.z / (de.z + 1e-6f) + fu.z;
        hv.w += nu.w / (de.w + 1e-6f) + fu.w;
        *reinterpret_cast<float4*>(h2 + hoff) = hv;
        s0 += hv.x; p0 += hv.x * hv.x;
        s1 += hv.y; p1 += hv.y * hv.y;
        s2v += hv.z; p2 += hv.z * hv.z;
        s3 += hv.w; p3 += hv.w * hv.w;
        if (n > 0)
            red_add_v4(&g_esumG[(size_t)g * 256 + c], se.x, se.y, se.z, se.w);
    }
    sStat[slot][c + 0] = s0; sStat[slot][c + 1] = s1;
    sStat[slot][c + 2] = s2v; sStat[slot][c + 3] = s3;
    sStat[slot + 4][c + 0] = p0; sStat[slot + 4][c + 1] = p1;
    sStat[slot + 4][c + 2] = p2; sStat[slot + 4][c + 3] = p3;
    __syncthreads();
    {
        int col = tid;
        float ssum = sStat[0][col] + sStat[1][col] + sStat[2][col] + sStat[3][col];
        float ssq  = sStat[4][col] + sStat[5][col] + sStat[6][col] + sStat[7][col];
        int bank = blockIdx.x & 7;
        atomicAdd(&g_sumB[bank][col], (double)ssum);
        atomicAdd(&g_sumsqB[bank][col], (double)ssq);
    }
}

// ------- stage 3: BN-apply h2 + per-graph sums + A_cat (restores zeros) ------
__global__ void graph_collect(float* __restrict__ h2, const float* __restrict__ u)
{
    int g = blockIdx.x;
    int c = threadIdx.x;
    float scA = g_bnA[c], scB = g_bnB[c];
    int a0 = g * APG;
    float sh = 0.f;
    for (int j = 0; j < APG; j++) {
        size_t off = (size_t)(a0 + j) * 256 + c;
        float v = h2[off];
        v = fmaxf(v * scA + scB, 0.f);
        h2[off] = v;
        sh += v;
    }
    float se = g_esumG[(size_t)g * 256 + c];
    g_esumG[(size_t)g * 256 + c] = 0.f;
    float sdeg = (float)(g_rowptr[(g + 1) * APG] - g_rowptr[g * APG]);
    float invd = 1.f / sdeg;
    g_Acat[(size_t)g * 768 + c]       = sh * (1.f / APG);
    g_Acat[(size_t)g * 768 + 256 + c] = se * invd;
    g_Acat[(size_t)g * 768 + 512 + c] = u[(size_t)g * 256 + c];
}

// ---------------- BN stats (u2) + apply --------------------------------------
__global__ void bn_stats(const float* __restrict__ X, int M, int set)
{
    int c = threadIdx.x;
    int r0 = blockIdx.x * 256;
    int r1 = min(r0 + 256, M);
    float s = 0.f, s2 = 0.f;
    for (int r = r0; r < r1; r++) {
        float v = X[(size_t)r * 256 + c];
        s += v; s2 += v * v;
    }
    int bank = blockIdx.x & 7;
    atomicAdd(&g_sumB[bank][set * 256 + c], (double)s);
    atomicAdd(&g_sumsqB[bank][set * 256 + c], (double)s2);
}

__global__ void bn_apply_u2(float* __restrict__ u2)
{
    int i = blockIdx.x * blockDim.x + threadIdx.x;
    if (i >= NG * 64) return;
    int a = i >> 6, q = i & 63;
    int c = q << 2;
    float4 sc = *reinterpret_cast<const float4*>(g_bnA + c);
    float4 bb = *reinterpret_cast<const float4*>(g_bnB + c);
    size_t off = (size_t)a * 256 + c;
    float4 v = *reinterpret_cast<const float4*>(u2 + off);
    v.x = fmaxf(v.x * sc.x + bb.x, 0.f);
    v.y = fmaxf(v.y * sc.y + bb.y, 0.f);
    v.z = fmaxf(v.z * sc.z + bb.z, 0.f);
    v.w = fmaxf(v.w * sc.w + bb.w, 0.f);
    *reinterpret_cast<float4*>(u2 + off) = v;
}

// ---------------- launch ------------------------------------------------------
extern "C" void kernel_launch(void* const* d_in, const int* in_sizes, int n_in,
                              void* d_out, int out_size)
{
    const float* h     = (const float*)d_in[0];
    const float* e     = (const float*)d_in[1];
    const float* u     = (const float*)d_in[2];
    const float* W     = (const float*)d_in[3];
    const float* b     = (const float*)d_in[4];
    const float* gamma = (const float*)d_in[5];
    const float* beta  = (const float*)d_in[6];
    const int*   src   = (const int*)d_in[7];
    const int*   dst   = (const int*)d_in[8];
    const int*   gid   = (const int*)d_in[9];

    float* out_h2 = (float*)d_out;
    float* out_e2 = out_h2 + (size_t)NA * 256;
    float* out_u2 = out_e2 + (size_t)NE * 256;

    float *pAh, *pEh, *pCu, *pFu, *pWt, *pBias, *pWcat, *pBcat, *pAcat;
    cudaGetSymbolAddress((void**)&pAh, g_Ah);
    cudaGetSymbolAddress((void**)&pEh, g_Eh);
    cudaGetSymbolAddress((void**)&pCu, g_Cu);
    cudaGetSymbolAddress((void**)&pFu, g_Fu);
    cudaGetSymbolAddress((void**)&pWt, g_Wt);
    cudaGetSymbolAddress((void**)&pBias, g_bias);
    cudaGetSymbolAddress((void**)&pWcat, g_Wcat);
    cudaGetSymbolAddress((void**)&pBcat, g_bcat);
    cudaGetSymbolAddress((void**)&pAcat, g_Acat);

    const int SMEM = 3 * 32768;   // 96 KB
    static int attr_done = 0;
    static cudaStream_t s2 = nullptr;
    static cudaEvent_t evFork = nullptr, evCSR = nullptr;
    if (!attr_done) {
        cudaFuncSetAttribute(sgemm_tc, cudaFuncAttributeMaxDynamicSharedMemorySize, SMEM);
        cudaStreamCreateWithFlags(&s2, cudaStreamNonBlocking);
        cudaEventCreateWithFlags(&evFork, cudaEventDisableTiming);
        cudaEventCreateWithFlags(&evCSR, cudaEventDisableTiming);
        attr_done = 1;
    }

    dim3 gH((NA + 127) / 128, 6);    // A,D,E on h
    dim3 gB((NE + 127) / 128, 2);    // B on e (+ edge assemble epilogue)
    dim3 gUU((NG + 127) / 128, 4);   // C,F on u
    dim3 gCat((NG + 127) / 128, 2);  // concatenated stage-3 GEMM

    transpose_W<<<(9 * 65536 + 255) / 256, 256>>>(W, b);   // also zeroes g_cnt

    // ---- CSR build on side stream (tiny kernels only, overlaps the GEMMs) ----
    cudaEventRecord(evFork, 0);
    cudaStreamWaitEvent(s2, evFork, 0);
    csr_hist<<<(NE + 255) / 256, 256, 0, s2>>>(dst);
    csr_scan<<<1, 1024, 0, s2>>>();
    csr_fill<<<(NE + 255) / 256, 256, 0, s2>>>(dst);
    cudaEventRecord(evCSR, s2);

    // ---- stage 1 (+ stage-2 GEMM inputs), single stream ----
    sgemm_tc<<<gUU, 256, SMEM>>>(u, pWt + 4 * 65536, pBias + 4 * 256,
                                 pCu, pFu, nullptr, NG, 256,
                                 nullptr, nullptr, nullptr);           // Cu, Fu
    sgemm_tc<<<gH, 256, SMEM>>>(h, pWt + 0 * 65536, pBias + 0 * 256,
                                pAh, out_h2, pEh, NA, 256,
                                nullptr, nullptr, nullptr);            // Ah, Dh, Eh
    sgemm_tc<<<gB, 256, SMEM>>>(e, pWt + 3 * 65536, pBias + 3 * 256,
                                out_e2, nullptr, nullptr, NE, 256,
                                src, dst, gid);                        // Be + assemble + stats1
    bn_finalize<<<1, 256>>>(1, NE, gamma + 256, beta + 256);

    // ---- stage 2: fused per-dst aggregation ----
    cudaStreamWaitEvent(0, evCSR, 0);
    edge_aggregate<<<2048, 256>>>(out_e2, out_h2, src, gid);
    bn_finalize<<<1, 256>>>(0, NA, gamma, beta);

    // ---- stage 3 ----
    graph_collect<<<NG, 256>>>(out_h2, u);                             // BN-apply h2 + A_cat
    sgemm_tc<<<gCat, 256, SMEM>>>(pAcat, pWcat, pBcat,
                                  out_u2, nullptr, nullptr, NG, 768,
                                  nullptr, nullptr, nullptr);          // u2 pre-BN
    bn_stats<<<(NG + 255) / 256, 256>>>(out_u2, NG, 2);
    bn_finalize<<<1, 256>>>(2, NG, gamma + 512, beta + 512);
    bn_apply_u2<<<(NG * 64 + 255) / 256, 256>>>(out_u2);
}

// round 16
// speedup vs baseline: 1.1352x; 1.1352x over previous
#include <cuda_runtime.h>
#include <cstdint>
#include <math.h>

#define NA 80000
#define NE 250000
#define NG 2000
#define APG 40

// ---------------- device scratch (no allocation allowed) ---------------------
__device__ float g_Ah[NA * 256];
__device__ float g_Eh[NA * 256];
__device__ float g_Cu[NG * 256];
__device__ float g_Fu[NG * 256];
__device__ float g_esumG[NG * 256];   // per-graph e2 sums; zero-restored by graph_collect
__device__ float g_Wt[6 * 256 * 256]; // slots 0..5, K-major, k-pair-permuted, tf32-rounded
__device__ float g_Wcat[256 * 768];   // [n][k] = W6|W7|W8 K-major, permuted, tf32-rounded
__device__ float g_bias[6 * 256];
__device__ float g_bcat[256];         // b6+b7+b8
__device__ float g_Acat[NG * 768];    // [Sh/40 | Se/deg | u]
__device__ double g_sumB[8][768];     // banked stats; zero-restored by bn_finalize
__device__ double g_sumsqB[8][768];
__device__ float g_bnA[256];
__device__ float g_bnB[256];
__device__ int g_cnt[NA];             // CSR: zeroed by transpose_W, hist, then cursor
__device__ int g_rowptr[NA + 1];
__device__ int g_eidx[NE];

// orig W idx -> slot:  W0->0(A) W1->3(B) W2->4(C) W3->1(D) W4->2(E) W5->5(F)
__constant__ int c_slot6[6] = {0, 3, 4, 1, 2, 5};

// ---------------- helpers -----------------------------------------------------
__device__ __forceinline__ uint32_t smem_u32(const void* p) {
    uint32_t a;
    asm("{ .reg .u64 t; cvta.to.shared.u64 t, %1; cvt.u32.u64 %0, t; }" : "=r"(a) : "l"(p));
    return a;
}
__device__ __forceinline__ uint32_t f2tf32(float v) {
    uint32_t u;
    asm("cvt.rna.tf32.f32 %0, %1;" : "=r"(u) : "f"(v));
    return u;
}
__device__ __forceinline__ void red_add_v4(float* addr, float a, float b, float c, float d) {
    asm volatile("red.global.add.v4.f32 [%0], {%1, %2, %3, %4};"
        :: "l"(addr), "f"(a), "f"(b), "f"(c), "f"(d) : "memory");
}

// ---------------- tf32 mma GEMM, 3-stage cp.async, swizzled smem -------------
// CTA tile 128x128. grid.x = 2*nSlots (w = x>>1 slot, half = x&1), grid.y = row
// blocks. x-major CTA enumeration makes all slot/half CTAs of the SAME A-rows
// adjacent in launch order -> A-operand fetched once from DRAM, rest L2 hits.
// Weights are k-pair-permuted per 32-chunk (p = (k%4)*8 + k/4) -> B LDS.64.
// If srcI != nullptr (edge-assemble mode): cooperative epilogue adds
// Ah[src]+Ah[dst]+Cu[gid[src]] and accumulates BN stats (set 1, banked).
__global__ void __launch_bounds__(256, 2) sgemm_tc(
    const float* __restrict__ A, const float* __restrict__ WtG,
    const float* __restrict__ biasG, float* __restrict__ C0,
    float* __restrict__ C1, float* __restrict__ C2, int M, int K,
    const int* __restrict__ srcI, const int* __restrict__ dstI,
    const int* __restrict__ gidI)
{
    extern __shared__ float sm[];
    const int tid  = threadIdx.x;
    const int lane = tid & 31;
    const int wid  = tid >> 5;
    const int wm   = wid & 1;
    const int wn   = wid >> 1;
    const int row0 = blockIdx.y * 128;
    const int w    = blockIdx.x >> 1;
    const int half = blockIdx.x & 1;
    const int col0 = half * 128;
    const int lq   = lane >> 2;
    const int lr   = lane & 3;

    const float* Wt   = WtG + (size_t)w * K * 256;
    const float* bias = biasG + w * 256;
    float* C = (w == 0) ? C0 : ((w == 1) ? C1 : C2);

    const uint32_t smbase = smem_u32(sm);
    const int chunks = K >> 5;

    auto load_chunk = [&](int c) {
        const int st = c % 3;
        const int k0 = c << 5;
        const uint32_t abase = smbase + st * 32768;
        const uint32_t bbase = abase + 16384;
#pragma unroll
        for (int ii = 0; ii < 4; ii++) {
            int i = tid + (ii << 8);
            int r = i >> 3, q = i & 7;
            int grow = row0 + r;
            const float* srcp = A + (size_t)grow * K + k0 + (q << 2);
            uint32_t dstA = abase + (uint32_t)((r << 5) + ((q ^ (r & 7)) << 2)) * 4;
            int sz = (grow < M) ? 16 : 0;
            asm volatile("cp.async.ca.shared.global [%0], [%1], 16, %2;"
                :: "r"(dstA), "l"(srcp), "r"(sz) : "memory");
        }
#pragma unroll
        for (int ii = 0; ii < 4; ii++) {
            int i = tid + (ii << 8);
            int n = i >> 3, q = i & 7;
            const float* srcp = Wt + (size_t)(col0 + n) * K + k0 + (q << 2);
            uint32_t dstB = bbase + (uint32_t)((n << 5) + ((q ^ (n & 7)) << 2)) * 4;
            asm volatile("cp.async.ca.shared.global [%0], [%1], 16;"
                :: "r"(dstB), "l"(srcp) : "memory");
        }
        asm volatile("cp.async.commit_group;" ::: "memory");
    };

    float acc[4][4][4];
#pragma unroll
    for (int i = 0; i < 4; i++)
#pragma unroll
        for (int j = 0; j < 4; j++)
#pragma unroll
            for (int r = 0; r < 4; r++) acc[i][j][r] = 0.f;

    load_chunk(0);
    if (chunks > 1) load_chunk(1);

    for (int c = 0; c < chunks; c++) {
        if (c + 1 < chunks) asm volatile("cp.async.wait_group 1;" ::: "memory");
        else                asm volatile("cp.async.wait_group 0;" ::: "memory");
        __syncthreads();
        if (c + 2 < chunks) load_chunk(c + 2);
        const float* sA = sm + (c % 3) * 8192;
        const float* sB = sA + 4096;

#pragma unroll
        for (int ks = 0; ks < 4; ks++) {
            const int s0 = (((2 * ks) ^ lq) << 2) + lr;
            const int s1 = (((2 * ks + 1) ^ lq) << 2) + lr;
            const int qp   = (lr << 1) + (ks >> 1);
            const int boff = ((qp ^ lq) << 2) + ((ks & 1) << 1);
            uint32_t bf[4][2];
#pragma unroll
            for (int nt = 0; nt < 4; nt++) {
                int n = wn * 32 + nt * 8 + lq;
                float2 b2 = *reinterpret_cast<const float2*>(&sB[(n << 5) + boff]);
                bf[nt][0] = __float_as_uint(b2.x);
                bf[nt][1] = __float_as_uint(b2.y);
            }
#pragma unroll
            for (int mt = 0; mt < 4; mt++) {
                int m = wm * 64 + mt * 16 + lq;
                uint32_t a0 = __float_as_uint(sA[(m << 5) + s0]);
                uint32_t a1 = __float_as_uint(sA[((m + 8) << 5) + s0]);
                uint32_t a2 = __float_as_uint(sA[(m << 5) + s1]);
                uint32_t a3 = __float_as_uint(sA[((m + 8) << 5) + s1]);
#pragma unroll
                for (int nt = 0; nt < 4; nt++) {
                    asm volatile(
                        "mma.sync.aligned.m16n8k8.row.col.f32.tf32.tf32.f32 "
                        "{%0,%1,%2,%3}, {%4,%5,%6,%7}, {%8,%9}, {%0,%1,%2,%3};"
                        : "+f"(acc[mt][nt][0]), "+f"(acc[mt][nt][1]),
                          "+f"(acc[mt][nt][2]), "+f"(acc[mt][nt][3])
                        : "r"(a0), "r"(a1), "r"(a2), "r"(a3),
                          "r"(bf[nt][0]), "r"(bf[nt][1]));
                }
            }
        }
    }

    if (srcI == nullptr) {
#pragma unroll
        for (int nt = 0; nt < 4; nt++) {
            int col = col0 + wn * 32 + nt * 8 + (lr << 1);
            float2 bv = *reinterpret_cast<const float2*>(bias + col);
#pragma unroll
            for (int mt = 0; mt < 4; mt++) {
                int rowa = row0 + wm * 64 + mt * 16 + lq;
                int rowb = rowa + 8;
                if (rowa < M) {
                    float2 o = make_float2(acc[mt][nt][0] + bv.x, acc[mt][nt][1] + bv.y);
                    *reinterpret_cast<float2*>(C + (size_t)rowa * 256 + col) = o;
                }
                if (rowb < M) {
                    float2 o = make_float2(acc[mt][nt][2] + bv.x, acc[mt][nt][3] + bv.y);
                    *reinterpret_cast<float2*>(C + (size_t)rowb * 256 + col) = o;
                }
            }
        }
    } else {
        // ---- cooperative edge-assemble epilogue ----
        float* sC = sm;
        float* sR = sm + 128 * 132;
        __syncthreads();
#pragma unroll
        for (int nt = 0; nt < 4; nt++) {
            int col = wn * 32 + nt * 8 + (lr << 1);
            float2 bv = *reinterpret_cast<const float2*>(bias + col0 + col);
#pragma unroll
            for (int mt = 0; mt < 4; mt++) {
                int ra = wm * 64 + mt * 16 + lq;
                *reinterpret_cast<float2*>(sC + ra * 132 + col) =
                    make_float2(acc[mt][nt][0] + bv.x, acc[mt][nt][1] + bv.y);
                *reinterpret_cast<float2*>(sC + (ra + 8) * 132 + col) =
                    make_float2(acc[mt][nt][2] + bv.x, acc[mt][nt][3] + bv.y);
            }
        }
        __syncthreads();

        const int cbase = lane << 2;
        float s0 = 0.f, s1 = 0.f, s2 = 0.f, s3 = 0.f;
        float p0 = 0.f, p1 = 0.f, p2 = 0.f, p3 = 0.f;
#pragma unroll 4
        for (int i = 0; i < 16; i++) {
            int r = wid * 16 + i;
            int row = row0 + r;
            if (row < M) {
                int s = srcI[row], d = dstI[row];
                int g = gidI[s];
                float4 a4 = *reinterpret_cast<const float4*>(sC + r * 132 + cbase);
                float4 x1 = *reinterpret_cast<const float4*>(g_Ah + (size_t)s * 256 + col0 + cbase);
                float4 x2 = *reinterpret_cast<const float4*>(g_Ah + (size_t)d * 256 + col0 + cbase);
                float4 x3 = *reinterpret_cast<const float4*>(g_Cu + (size_t)g * 256 + col0 + cbase);
                float vx = a4.x + x1.x + x2.x + x3.x;
                float vy = a4.y + x1.y + x2.y + x3.y;
                float vz = a4.z + x1.z + x2.z + x3.z;
                float vw = a4.w + x1.w + x2.w + x3.w;
                *reinterpret_cast<float4*>(C + (size_t)row * 256 + col0 + cbase) =
                    make_float4(vx, vy, vz, vw);
                s0 += vx; p0 += vx * vx;
                s1 += vy; p1 += vy * vy;
                s2 += vz; p2 += vz * vz;
                s3 += vw; p3 += vw * vw;
            }
        }
        sR[wid * 256 + cbase + 0] = s0;
        sR[wid * 256 + cbase + 1] = s1;
        sR[wid * 256 + cbase + 2] = s2;
        sR[wid * 256 + cbase + 3] = s3;
        sR[wid * 256 + 128 + cbase + 0] = p0;
        sR[wid * 256 + 128 + cbase + 1] = p1;
        sR[wid * 256 + 128 + cbase + 2] = p2;
        sR[wid * 256 + 128 + cbase + 3] = p3;
        __syncthreads();
        {
            int c = tid & 127;
            int issq = tid >> 7;
            float acc8 = 0.f;
#pragma unroll
            for (int ww = 0; ww < 8; ww++)
                acc8 += sR[ww * 256 + issq * 128 + c];
            int bank = blockIdx.y & 7;
            if (issq) atomicAdd(&g_sumsqB[bank][256 + col0 + c], (double)acc8);
            else      atomicAdd(&g_sumB[bank][256 + col0 + c], (double)acc8);
        }
    }
}

// ---------------- weight prep (k-pair permutation baked in) + cnt zero -------
__global__ void transpose_W(const float* __restrict__ W, const float* __restrict__ b) {
    int idx = blockIdx.x * 256 + threadIdx.x;
    if (idx < 9 * 65536) {
        int w = idx >> 16;
        int rc = idx & 65535;
        int r = rc >> 8, c = rc & 255;       // r = k, c = n
        float v = __uint_as_float(f2tf32(W[idx]));
        int kin = r & 31;
        int kp  = (r & ~31) + ((kin & 3) << 3) + (kin >> 2);
        if (w < 6) g_Wt[(c_slot6[w] << 16) + (c << 8) + kp] = v;
        else {
            int kglob = (w - 6) * 256 + r;
            int kin2 = kglob & 31;
            int kp2  = (kglob & ~31) + ((kin2 & 3) << 3) + (kin2 >> 2);
            g_Wcat[c * 768 + kp2] = v;
        }
    }
    if (idx < 6 * 256) {
        int w = idx >> 8;
        g_bias[(c_slot6[w] << 8) + (idx & 255)] = b[idx];
    }
    if (idx < 256) {
        g_bcat[idx] = b[6 * 256 + idx] + b[7 * 256 + idx] + b[8 * 256 + idx];
    }
    if (idx < NA) g_cnt[idx] = 0;
}

// ---------------- CSR build ---------------------------------------------------
__global__ void csr_hist(const int* __restrict__ dst) {
    int e = blockIdx.x * blockDim.x + threadIdx.x;
    if (e < NE) atomicAdd(&g_cnt[dst[e]], 1);
}

__global__ void csr_scan() {
    __shared__ int wsum[32];
    __shared__ int carry_s;
    int tid = threadIdx.x, lane = tid & 31, wd = tid >> 5;
    if (tid == 0) carry_s = 0;
    __syncthreads();
    for (int base = 0; base < NA; base += 1024) {
        int i = base + tid;
        int v = (i < NA) ? g_cnt[i] : 0;
        int x = v;
#pragma unroll
        for (int off = 1; off < 32; off <<= 1) {
            int t = __shfl_up_sync(0xffffffff, x, off);
            if (lane >= off) x += t;
        }
        if (lane == 31) wsum[wd] = x;
        __syncthreads();
        if (wd == 0) {
            int wv = wsum[lane];
#pragma unroll
            for (int off = 1; off < 32; off <<= 1) {
                int t = __shfl_up_sync(0xffffffff, wv, off);
                if (lane >= off) wv += t;
            }
            wsum[lane] = wv;
        }
        __syncthreads();
        int warp_excl = (wd == 0) ? 0 : wsum[wd - 1];
        int excl = carry_s + warp_excl + x - v;
        if (i < NA) { g_rowptr[i] = excl; g_cnt[i] = excl; }
        __syncthreads();
        if (tid == 0) carry_s += wsum[31];
        __syncthreads();
    }
    if (tid == 0) g_rowptr[NA] = carry_s;
}

__global__ void csr_fill(const int* __restrict__ dst) {
    int e = blockIdx.x * blockDim.x + threadIdx.x;
    if (e < NE) {
        int p = atomicAdd(&g_cnt[dst[e]], 1);
        g_eidx[p] = e;
    }
}

// ---------------- BN finalize (sums banks, restores zeros) -------------------
__global__ void bn_finalize(int set, int M, const float* __restrict__ gam,
                            const float* __restrict__ bet)
{
    int c = threadIdx.x;
    double s = 0.0, s2 = 0.0;
#pragma unroll
    for (int k = 0; k < 8; k++) {
        s  += g_sumB[k][set * 256 + c];
        s2 += g_sumsqB[k][set * 256 + c];
        g_sumB[k][set * 256 + c] = 0.0;
        g_sumsqB[k][set * 256 + c] = 0.0;
    }
    double mean = s / M;
    double var  = s2 / M - mean * mean;
    float scale = gam[c] * rsqrtf((float)(var + 1e-5));
    g_bnA[c] = scale;
    g_bnB[c] = bet[c] - (float)mean * scale;
}

// -------- fused per-dst: BN(e2)+relu (in place) + gated agg + h2 + stats0 ----
__global__ void __launch_bounds__(256) edge_aggregate(
    float* __restrict__ e2, float* __restrict__ h2,
    const int* __restrict__ src, const int* __restrict__ gid)
{
    int tid = threadIdx.x;
    int q = tid & 63;
    int slot = tid >> 6;
    int c = q << 2;
    float4 sc = *reinterpret_cast<const float4*>(g_bnA + c);
    float4 bb = *reinterpret_cast<const float4*>(g_bnB + c);
    float s0 = 0.f, s1 = 0.f, s2 = 0.f, s3 = 0.f;
    float p0 = 0.f, p1 = 0.f, p2 = 0.f, p3 = 0.f;

    for (int d = blockIdx.x * 4 + slot; d < NA; d += gridDim.x * 4) {
        int beg = g_rowptr[d], end = g_rowptr[d + 1];
        float4 nu = make_float4(0.f, 0.f, 0.f, 0.f);
        float4 de = make_float4(0.f, 0.f, 0.f, 0.f);
        float4 se = make_float4(0.f, 0.f, 0.f, 0.f);
        for (int i = beg; i < end; i++) {
            int eid = g_eidx[i];
            int s = src[eid];
            size_t off = (size_t)eid * 256 + c;
            float4 v = *reinterpret_cast<const float4*>(e2 + off);
            v.x = fmaxf(v.x * sc.x + bb.x, 0.f);
            v.y = fmaxf(v.y * sc.y + bb.y, 0.f);
            v.z = fmaxf(v.z * sc.z + bb.z, 0.f);
            v.w = fmaxf(v.w * sc.w + bb.w, 0.f);
            *reinterpret_cast<float4*>(e2 + off) = v;
            float4 eh = *reinterpret_cast<const float4*>(g_Eh + (size_t)s * 256 + c);
            float g0 = 1.f / (1.f + __expf(-v.x));
            float g1 = 1.f / (1.f + __expf(-v.y));
            float g2 = 1.f / (1.f + __expf(-v.z));
            float g3 = 1.f / (1.f + __expf(-v.w));
            nu.x += g0 * eh.x; nu.y += g1 * eh.y; nu.z += g2 * eh.z; nu.w += g3 * eh.w;
            de.x += g0; de.y += g1; de.z += g2; de.w += g3;
            se.x += v.x; se.y += v.y; se.z += v.z; se.w += v.w;
        }
        int g = gid[d];
        size_t hoff = (size_t)d * 256 + c;
        float4 hv = *reinterpret_cast<const float4*>(h2 + hoff);
        float4 fu = *reinterpret_cast<const float4*>(g_Fu + (size_t)g * 256 + c);
        hv.x += nu.x / (de.x + 1e-6f) + fu.x;
        hv.y += nu.y / (de.y + 1e-6f) + fu.y;
        hv.z += nu.z / (de.z + 1e-6f) + fu.z;
        hv.w += nu.w / (de.w + 1e-6f) + fu.w;
        *reinterpret_cast<float4*>(h2 + hoff) = hv;
        s0 += hv.x; p0 += hv.x * hv.x;
        s1 += hv.y; p1 += hv.y * hv.y;
        s2 += hv.z; p2 += hv.z * hv.z;
        s3 += hv.w; p3 += hv.w * hv.w;
        if (end > beg)
            red_add_v4(&g_esumG[(size_t)g * 256 + c], se.x, se.y, se.z, se.w);
    }
    int bank = blockIdx.x & 7;
    atomicAdd(&g_sumB[bank][c + 0], (double)s0); atomicAdd(&g_sumsqB[bank][c + 0], (double)p0);
    atomicAdd(&g_sumB[bank][c + 1], (double)s1); atomicAdd(&g_sumsqB[bank][c + 1], (double)p1);
    atomicAdd(&g_sumB[bank][c + 2], (double)s2); atomicAdd(&g_sumsqB[bank][c + 2], (double)p2);
    atomicAdd(&g_sumB[bank][c + 3], (double)s3); atomicAdd(&g_sumsqB[bank][c + 3], (double)p3);
}

// ------- stage 3: BN-apply h2 + per-graph sums + A_cat (restores zeros) ------
__global__ void graph_collect(float* __restrict__ h2, const float* __restrict__ u)
{
    int g = blockIdx.x;
    int c = threadIdx.x;
    float scA = g_bnA[c], scB = g_bnB[c];
    int a0 = g * APG;
    float sh = 0.f;
    for (int j = 0; j < APG; j++) {
        size_t off = (size_t)(a0 + j) * 256 + c;
        float v = h2[off];
        v = fmaxf(v * scA + scB, 0.f);
        h2[off] = v;
        sh += v;
    }
    float se = g_esumG[(size_t)g * 256 + c];
    g_esumG[(size_t)g * 256 + c] = 0.f;
    float sdeg = (float)(g_rowptr[(g + 1) * APG] - g_rowptr[g * APG]);
    float invd = 1.f / sdeg;
    g_Acat[(size_t)g * 768 + c]       = sh * (1.f / APG);
    g_Acat[(size_t)g * 768 + 256 + c] = se * invd;
    g_Acat[(size_t)g * 768 + 512 + c] = u[(size_t)g * 256 + c];
}

// ---------------- BN stats (u2) + apply --------------------------------------
__global__ void bn_stats(const float* __restrict__ X, int M, int set)
{
    int c = threadIdx.x;
    int r0 = blockIdx.x * 256;
    int r1 = min(r0 + 256, M);
    float s = 0.f, s2 = 0.f;
    for (int r = r0; r < r1; r++) {
        float v = X[(size_t)r * 256 + c];
        s += v; s2 += v * v;
    }
    int bank = blockIdx.x & 7;
    atomicAdd(&g_sumB[bank][set * 256 + c], (double)s);
    atomicAdd(&g_sumsqB[bank][set * 256 + c], (double)s2);
}

__global__ void bn_apply_u2(float* __restrict__ u2)
{
    int i = blockIdx.x * blockDim.x + threadIdx.x;
    if (i >= NG * 64) return;
    int a = i >> 6, q = i & 63;
    int c = q << 2;
    float4 sc = *reinterpret_cast<const float4*>(g_bnA + c);
    float4 bb = *reinterpret_cast<const float4*>(g_bnB + c);
    size_t off = (size_t)a * 256 + c;
    float4 v = *reinterpret_cast<const float4*>(u2 + off);
    v.x = fmaxf(v.x * sc.x + bb.x, 0.f);
    v.y = fmaxf(v.y * sc.y + bb.y, 0.f);
    v.z = fmaxf(v.z * sc.z + bb.z, 0.f);
    v.w = fmaxf(v.w * sc.w + bb.w, 0.f);
    *reinterpret_cast<float4*>(u2 + off) = v;
}

// ---------------- launch ------------------------------------------------------
extern "C" void kernel_launch(void* const* d_in, const int* in_sizes, int n_in,
                              void* d_out, int out_size)
{
    const float* h     = (const float*)d_in[0];
    const float* e     = (const float*)d_in[1];
    const float* u     = (const float*)d_in[2];
    const float* W     = (const float*)d_in[3];
    const float* b     = (const float*)d_in[4];
    const float* gamma = (const float*)d_in[5];
    const float* beta  = (const float*)d_in[6];
    const int*   src   = (const int*)d_in[7];
    const int*   dst   = (const int*)d_in[8];
    const int*   gid   = (const int*)d_in[9];

    float* out_h2 = (float*)d_out;
    float* out_e2 = out_h2 + (size_t)NA * 256;
    float* out_u2 = out_e2 + (size_t)NE * 256;

    float *pAh, *pEh, *pCu, *pFu, *pWt, *pBias, *pWcat, *pBcat, *pAcat;
    cudaGetSymbolAddress((void**)&pAh, g_Ah);
    cudaGetSymbolAddress((void**)&pEh, g_Eh);
    cudaGetSymbolAddress((void**)&pCu, g_Cu);
    cudaGetSymbolAddress((void**)&pFu, g_Fu);
    cudaGetSymbolAddress((void**)&pWt, g_Wt);
    cudaGetSymbolAddress((void**)&pBias, g_bias);
    cudaGetSymbolAddress((void**)&pWcat, g_Wcat);
    cudaGetSymbolAddress((void**)&pBcat, g_bcat);
    cudaGetSymbolAddress((void**)&pAcat, g_Acat);

    const int SMEM = 3 * 32768;   // 96 KB
    static int attr_done = 0;
    static cudaStream_t s2 = nullptr;
    static cudaEvent_t evFork = nullptr, evCSR = nullptr;
    if (!attr_done) {
        cudaFuncSetAttribute(sgemm_tc, cudaFuncAttributeMaxDynamicSharedMemorySize, SMEM);
        cudaStreamCreateWithFlags(&s2, cudaStreamNonBlocking);
        cudaEventCreateWithFlags(&evFork, cudaEventDisableTiming);
        cudaEventCreateWithFlags(&evCSR, cudaEventDisableTiming);
        attr_done = 1;
    }

    // grid: x = slot/half combos (A-row reuse adjacent), y = row blocks
    dim3 gH(6, (NA + 127) / 128);    // A,D,E on h
    dim3 gB(2, (NE + 127) / 128);    // B on e (+ edge assemble epilogue)
    dim3 gUU(4, (NG + 127) / 128);   // C,F on u
    dim3 gCat(2, (NG + 127) / 128);  // concatenated stage-3 GEMM

    transpose_W<<<(9 * 65536 + 255) / 256, 256>>>(W, b);   // also zeroes g_cnt

    // ---- CSR build on side stream (tiny kernels only, overlaps the GEMMs) ----
    cudaEventRecord(evFork, 0);
    cudaStreamWaitEvent(s2, evFork, 0);
    csr_hist<<<(NE + 255) / 256, 256, 0, s2>>>(dst);
    csr_scan<<<1, 1024, 0, s2>>>();
    csr_fill<<<(NE + 255) / 256, 256, 0, s2>>>(dst);
    cudaEventRecord(evCSR, s2);

    // ---- stage 1 (+ stage-2 GEMM inputs), single stream ----
    sgemm_tc<<<gUU, 256, SMEM>>>(u, pWt + 4 * 65536, pBias + 4 * 256,
                                 pCu, pFu, nullptr, NG, 256,
                                 nullptr, nullptr, nullptr);           // Cu, Fu
    sgemm_tc<<<gH, 256, SMEM>>>(h, pWt + 0 * 65536, pBias + 0 * 256,
                                pAh, out_h2, pEh, NA, 256,
                                nullptr, nullptr, nullptr);            // Ah, Dh, Eh
    sgemm_tc<<<gB, 256, SMEM>>>(e, pWt + 3 * 65536, pBias + 3 * 256,
                                out_e2, nullptr, nullptr, NE, 256,
                                src, dst, gid);                        // Be + assemble + stats1
    bn_finalize<<<1, 256>>>(1, NE, gamma + 256, beta + 256);

    // ---- stage 2: fused per-dst aggregation ----
    cudaStreamWaitEvent(0, evCSR, 0);
    edge_aggregate<<<1024, 256>>>(out_e2, out_h2, src, gid);
    bn_finalize<<<1, 256>>>(0, NA, gamma, beta);

    // ---- stage 3 ----
    graph_collect<<<NG, 256>>>(out_h2, u);                             // BN-apply h2 + A_cat
    sgemm_tc<<<gCat, 256, SMEM>>>(pAcat, pWcat, pBcat,
                                  out_u2, nullptr, nullptr, NG, 768,
                                  nullptr, nullptr, nullptr);          // u2 pre-BN
    bn_stats<<<(NG + 255) / 256, 256>>>(out_u2, NG, 2);
    bn_finalize<<<1, 256>>>(2, NG, gamma + 512, beta + 512);
    bn_apply_u2<<<(NG * 64 + 255) / 256, 256>>>(out_u2);
}